// round 3
// baseline (speedup 1.0000x reference)
#include <cuda_runtime.h>
#include <cuda_bf16.h>
#include <cstdint>
#include <cstddef>

#define BATCH 1024
#define NA 48
#define NB 24
#define DIM 680
#define GTOT (NA*NB*NA)          // 55296
#define SPLITK 8
#define KPS (GTOT/SPLITK)        // 6912
#define BK 32
#define KITERS (KPS/BK)          // 216
#define BM 128                   // i-tile
#define BNJ 64                   // j-tile
#define APITCH 136               // halves: 128 + 8 pad (odd multiple of 8 -> conflict-free ldmatrix)
#define BPITCH 72                // halves: 64 + 8 pad
#define FPITCH 40                // halves: 32 + 8 pad
#define MPITCH 136
#define NDIM2 (DIM*DIM)

// ---- scratch (no allocations allowed) ----
__device__ float gP1[(size_t)SPLITK * NDIM2];   // Zh^T Zh partials
__device__ float gP2[(size_t)SPLITK * NDIM2];   // Zh^T Zl partials
__device__ float gS1[NDIM2];
__device__ float gS2[NDIM2];
__device__ float gM[NDIM2];

// ---------------------------------------------------------------- helpers
__device__ __forceinline__ uint32_t smem_u32(const void* p) {
    return (uint32_t)__cvta_generic_to_shared(p);
}
__device__ __forceinline__ void ldsm4t(uint32_t (&r)[4], uint32_t addr) {
    asm volatile("ldmatrix.sync.aligned.m8n8.x4.trans.shared.b16 {%0,%1,%2,%3}, [%4];"
                 : "=r"(r[0]), "=r"(r[1]), "=r"(r[2]), "=r"(r[3]) : "r"(addr));
}
__device__ __forceinline__ void ldsm4(uint32_t (&r)[4], uint32_t addr) {
    asm volatile("ldmatrix.sync.aligned.m8n8.x4.shared.b16 {%0,%1,%2,%3}, [%4];"
                 : "=r"(r[0]), "=r"(r[1]), "=r"(r[2]), "=r"(r[3]) : "r"(addr));
}
__device__ __forceinline__ void mma_bf16(float (&d)[4], const uint32_t (&a)[4],
                                         uint32_t b0, uint32_t b1) {
    asm volatile(
        "mma.sync.aligned.m16n8k16.row.col.f32.bf16.bf16.f32 "
        "{%0,%1,%2,%3}, {%4,%5,%6,%7}, {%8,%9}, {%0,%1,%2,%3};\n"
        : "+f"(d[0]), "+f"(d[1]), "+f"(d[2]), "+f"(d[3])
        : "r"(a[0]), "r"(a[1]), "r"(a[2]), "r"(a[3]), "r"(b0), "r"(b1));
}
__device__ __forceinline__ uint32_t pack2(float x, float y) {
    __nv_bfloat162 h = __floats2bfloat162_rn(x, y);
    return *reinterpret_cast<uint32_t*>(&h);
}
// split z into bf16 hi + bf16 lo
__device__ __forceinline__ void split_bf16(float z, __nv_bfloat16& h, __nv_bfloat16& l) {
    h = __float2bfloat16(z);
    l = __float2bfloat16(z - __bfloat162float(h));
}

// ---------------------------------------------------------------- kernel 1
// C1 = Zh^T Zh -> gP1[split], C2 = Zh^T Zl -> gP2[split],  Z = sqrt(w) * D
extern "C" __global__ void __launch_bounds__(256)
gram_kernel(const float* __restrict__ D, const float* __restrict__ qw) {
    __shared__ __nv_bfloat16 sA[2][BK * APITCH];
    __shared__ __nv_bfloat16 sBh[2][BK * BPITCH];
    __shared__ __nv_bfloat16 sBl[2][BK * BPITCH];
    __shared__ float sqw[NB];

    const int tid   = threadIdx.x;
    const int ibase = blockIdx.x * BM;
    const int jbase = blockIdx.y * BNJ;
    const int g0    = blockIdx.z * KPS;

    if (tid < NB) sqw[tid] = sqrtf(qw[tid]);
    __syncthreads();

    // global-load mapping
    const int  ca = ibase + (tid & 31) * 4;   // A: 32 float4 per row, 8 rows/pass x4
    const int  cb = jbase + (tid & 15) * 4;   // B: 16 float4 per row, 16 rows/pass x2
    const bool avalid = ca < DIM;
    const bool bvalid = cb < DIM;
    const int  rA = tid >> 5;
    const int  rB = tid >> 4;

    // fragment mapping
    const int lane = tid & 31, warp = tid >> 5;
    const int wm  = (warp & 1) * 64;
    const int wn  = (warp >> 1) * 32;          // 0,32 -> C1 ; 64,96 -> C2
    const int wnl = wn & 63;
    const bool useLo = (wn >= 64);
    const int group = lane >> 2, tig = lane & 3;
    const int arow = (lane & 7) + ((lane & 16) ? 8 : 0);
    const int acol = (lane & 8) ? 8 : 0;
    const int brow = (lane & 7) + ((lane & 8) ? 8 : 0);
    const int bcol = (lane & 16) ? 8 : 0;

    const uint32_t aU[2]  = { smem_u32(sA[0]),  smem_u32(sA[1])  };
    const uint32_t bhU[2] = { smem_u32(sBh[0]), smem_u32(sBh[1]) };
    const uint32_t blU[2] = { smem_u32(sBl[0]), smem_u32(sBl[1]) };

    float acc[4][4][4];
#pragma unroll
    for (int mi = 0; mi < 4; mi++)
#pragma unroll
        for (int nb = 0; nb < 4; nb++)
#pragma unroll
            for (int r = 0; r < 4; r++) acc[mi][nb][r] = 0.f;

    float4 aP[4], bP[2];

    auto ldg = [&](int it) {
        const int gg = g0 + it * BK;
#pragma unroll
        for (int p = 0; p < 4; p++) {
            int g = gg + rA + 8 * p;
            aP[p] = avalid ? *(const float4*)(D + (size_t)g * DIM + ca)
                           : make_float4(0.f, 0.f, 0.f, 0.f);
        }
#pragma unroll
        for (int p = 0; p < 2; p++) {
            int g = gg + rB + 16 * p;
            bP[p] = bvalid ? *(const float4*)(D + (size_t)g * DIM + cb)
                           : make_float4(0.f, 0.f, 0.f, 0.f);
        }
    };
    auto sts = [&](int buf, int it) {
        const int gg = g0 + it * BK;
#pragma unroll
        for (int p = 0; p < 4; p++) {
            int g = gg + rA + 8 * p;
            float w = sqw[(g / NA) % NB];
            float4 v = aP[p];
            uint2 u;
            u.x = pack2(v.x * w, v.y * w);
            u.y = pack2(v.z * w, v.w * w);
            *(uint2*)&sA[buf][(rA + 8 * p) * APITCH + (tid & 31) * 4] = u;
        }
#pragma unroll
        for (int p = 0; p < 2; p++) {
            int g = gg + rB + 16 * p;
            float w = sqw[(g / NA) % NB];
            float4 v = bP[p];
            __nv_bfloat16 h[4], l[4];
            split_bf16(v.x * w, h[0], l[0]);
            split_bf16(v.y * w, h[1], l[1]);
            split_bf16(v.z * w, h[2], l[2]);
            split_bf16(v.w * w, h[3], l[3]);
            int off = (rB + 16 * p) * BPITCH + (tid & 15) * 4;
            uint2 uh, ul;
            uh.x = pack2(__bfloat162float(h[0]), __bfloat162float(h[1]));
            uh.y = pack2(__bfloat162float(h[2]), __bfloat162float(h[3]));
            ul.x = pack2(__bfloat162float(l[0]), __bfloat162float(l[1]));
            ul.y = pack2(__bfloat162float(l[2]), __bfloat162float(l[3]));
            *(uint2*)&sBh[buf][off] = uh;
            *(uint2*)&sBl[buf][off] = ul;
        }
    };

    ldg(0);
    sts(0, 0);
    __syncthreads();

    for (int it = 0; it < KITERS; ++it) {
        const int cur = it & 1;
        if (it + 1 < KITERS) ldg(it + 1);

        const uint32_t abase = aU[cur];
        const uint32_t bbase = useLo ? blU[cur] : bhU[cur];
#pragma unroll
        for (int kk = 0; kk < BK; kk += 16) {
            uint32_t A4[4][4], B4[2][4];
#pragma unroll
            for (int mi = 0; mi < 4; mi++)
                ldsm4t(A4[mi], abase + 2u * ((kk + arow) * APITCH + wm + 16 * mi + acol));
#pragma unroll
            for (int h = 0; h < 2; h++)
                ldsm4t(B4[h], bbase + 2u * ((kk + brow) * BPITCH + wnl + 16 * h + bcol));
#pragma unroll
            for (int mi = 0; mi < 4; mi++)
#pragma unroll
                for (int nb = 0; nb < 4; nb++) {
                    const int h = nb >> 1, pr = (nb & 1) * 2;
                    mma_bf16(acc[mi][nb], A4[mi], B4[h][pr], B4[h][pr + 1]);
                }
        }
        if (it + 1 < KITERS) sts((it + 1) & 1, it + 1);
        __syncthreads();
    }

    // epilogue: write C1 / C2 partials
    float* P = (useLo ? gP2 : gP1) + (size_t)blockIdx.z * NDIM2;
#pragma unroll
    for (int mi = 0; mi < 4; mi++) {
        int i1 = ibase + wm + 16 * mi + group;
        int i2 = i1 + 8;
#pragma unroll
        for (int nb = 0; nb < 4; nb++) {
            int j0 = jbase + wnl + 8 * nb + 2 * tig;
            if (j0 < DIM) {
                if (i1 < DIM) {
                    P[(size_t)i1 * DIM + j0]     = acc[mi][nb][0];
                    P[(size_t)i1 * DIM + j0 + 1] = acc[mi][nb][1];
                }
                if (i2 < DIM) {
                    P[(size_t)i2 * DIM + j0]     = acc[mi][nb][2];
                    P[(size_t)i2 * DIM + j0 + 1] = acc[mi][nb][3];
                }
            }
        }
    }
}

// ---------------------------------------------------------------- kernel 2
extern "C" __global__ void reduce_kernel() {
    int idx = blockIdx.x * blockDim.x + threadIdx.x;
    if (idx < NDIM2) {
        float s1 = 0.f, s2 = 0.f;
#pragma unroll
        for (int p = 0; p < SPLITK; p++) {
            s1 += gP1[(size_t)p * NDIM2 + idx];
            s2 += gP2[(size_t)p * NDIM2 + idx];
        }
        gS1[idx] = s1;
        gS2[idx] = s2;
    }
}

// ---------------------------------------------------------------- kernel 3
// M = S1 + S2 + S2^T
extern "C" __global__ void sym_kernel() {
    int idx = blockIdx.x * blockDim.x + threadIdx.x;
    if (idx < NDIM2) {
        int i = idx / DIM;
        int j = idx - i * DIM;
        gM[idx] = gS1[idx] + gS2[idx] + gS2[(size_t)j * DIM + i];
    }
}

// ---------------------------------------------------------------- kernel 4
// out = F @ M  with 3-term bf16 split: Fh*Mh + Fh*Ml + Fl*Mh
extern "C" __global__ void __launch_bounds__(256)
out_kernel(const float* __restrict__ F, float* __restrict__ out) {
    __shared__ __nv_bfloat16 sFh[BM * FPITCH], sFl[BM * FPITCH];
    __shared__ __nv_bfloat16 sMh[BK * MPITCH], sMl[BK * MPITCH];

    const int tid   = threadIdx.x;
    const int nbase = blockIdx.x * BM;     // 1024/128 exact
    const int ibase = blockIdx.y * BM;     // 6 * 128 = 768 padded

    const int lane = tid & 31, warp = tid >> 5;
    const int wm = (warp & 1) * 64;
    const int wn = (warp >> 1) * 32;
    const int group = lane >> 2, tig = lane & 3;
    // non-trans A frag offsets (F stored [m][k])
    const int frow = ((lane & 8) ? 8 : 0) + (lane & 7);
    const int fcol = (lane & 16) ? 8 : 0;
    // trans B frag offsets (M stored [k][n])
    const int brow = (lane & 7) + ((lane & 8) ? 8 : 0);
    const int bcol = (lane & 16) ? 8 : 0;

    const uint32_t fhU = smem_u32(sFh), flU = smem_u32(sFl);
    const uint32_t mhU = smem_u32(sMh), mlU = smem_u32(sMl);

    float acc[4][4][4];
#pragma unroll
    for (int mi = 0; mi < 4; mi++)
#pragma unroll
        for (int nb = 0; nb < 4; nb++)
#pragma unroll
            for (int r = 0; r < 4; r++) acc[mi][nb][r] = 0.f;

    const int NIT = (DIM + BK - 1) / BK;  // 22

    for (int it = 0; it < NIT; ++it) {
        const int k0 = it * BK;
        // load F tile [128 n][32 k]
        {
            const int c = (tid & 7) * 4;
            const bool v = (k0 + c) < DIM;
#pragma unroll
            for (int p = 0; p < 4; p++) {
                int row = (tid >> 3) + 32 * p;
                float4 f = v ? *(const float4*)(F + (size_t)(nbase + row) * DIM + k0 + c)
                             : make_float4(0.f, 0.f, 0.f, 0.f);
                __nv_bfloat16 h[4], l[4];
                split_bf16(f.x, h[0], l[0]);
                split_bf16(f.y, h[1], l[1]);
                split_bf16(f.z, h[2], l[2]);
                split_bf16(f.w, h[3], l[3]);
                int off = row * FPITCH + c;
                uint2 uh, ul;
                uh.x = pack2(__bfloat162float(h[0]), __bfloat162float(h[1]));
                uh.y = pack2(__bfloat162float(h[2]), __bfloat162float(h[3]));
                ul.x = pack2(__bfloat162float(l[0]), __bfloat162float(l[1]));
                ul.y = pack2(__bfloat162float(l[2]), __bfloat162float(l[3]));
                *(uint2*)&sFh[off] = uh;
                *(uint2*)&sFl[off] = ul;
            }
        }
        // load M tile [32 k][128 i]
        {
            const int c = (tid & 31) * 4;
            const bool cv = (ibase + c) < DIM;
#pragma unroll
            for (int p = 0; p < 4; p++) {
                int r = (tid >> 5) + 8 * p;
                int j = k0 + r;
                bool v = cv && (j < DIM);
                float4 m = v ? *(const float4*)(gM + (size_t)j * DIM + ibase + c)
                             : make_float4(0.f, 0.f, 0.f, 0.f);
                __nv_bfloat16 h[4], l[4];
                split_bf16(m.x, h[0], l[0]);
                split_bf16(m.y, h[1], l[1]);
                split_bf16(m.z, h[2], l[2]);
                split_bf16(m.w, h[3], l[3]);
                int off = r * MPITCH + c;
                uint2 uh, ul;
                uh.x = pack2(__bfloat162float(h[0]), __bfloat162float(h[1]));
                uh.y = pack2(__bfloat162float(h[2]), __bfloat162float(h[3]));
                ul.x = pack2(__bfloat162float(l[0]), __bfloat162float(l[1]));
                ul.y = pack2(__bfloat162float(l[2]), __bfloat162float(l[3]));
                *(uint2*)&sMh[off] = uh;
                *(uint2*)&sMl[off] = ul;
            }
        }
        __syncthreads();

#pragma unroll
        for (int kk = 0; kk < BK; kk += 16) {
            uint32_t Ah[4][4], Al[4][4], Bh[2][4], Bl[2][4];
#pragma unroll
            for (int mi = 0; mi < 4; mi++) {
                uint32_t off = 2u * ((wm + 16 * mi + frow) * FPITCH + kk + fcol);
                ldsm4(Ah[mi], fhU + off);
                ldsm4(Al[mi], flU + off);
            }
#pragma unroll
            for (int h = 0; h < 2; h++) {
                uint32_t off = 2u * ((kk + brow) * MPITCH + wn + 16 * h + bcol);
                ldsm4t(Bh[h], mhU + off);
                ldsm4t(Bl[h], mlU + off);
            }
#pragma unroll
            for (int mi = 0; mi < 4; mi++)
#pragma unroll
                for (int nb = 0; nb < 4; nb++) {
                    const int h = nb >> 1, pr = (nb & 1) * 2;
                    mma_bf16(acc[mi][nb], Ah[mi], Bh[h][pr], Bh[h][pr + 1]);
                    mma_bf16(acc[mi][nb], Ah[mi], Bl[h][pr], Bl[h][pr + 1]);
                    mma_bf16(acc[mi][nb], Al[mi], Bh[h][pr], Bh[h][pr + 1]);
                }
        }
        __syncthreads();
    }

#pragma unroll
    for (int mi = 0; mi < 4; mi++) {
        int n1 = nbase + wm + 16 * mi + group;
        int n2 = n1 + 8;
#pragma unroll
        for (int nb = 0; nb < 4; nb++) {
            int i0 = ibase + wn + 8 * nb + 2 * tig;
            if (i0 < DIM) {
                out[(size_t)n1 * DIM + i0]     = acc[mi][nb][0];
                out[(size_t)n1 * DIM + i0 + 1] = acc[mi][nb][1];
                out[(size_t)n2 * DIM + i0]     = acc[mi][nb][2];
                out[(size_t)n2 * DIM + i0 + 1] = acc[mi][nb][3];
            }
        }
    }
}

// ---------------------------------------------------------------- launch
extern "C" void kernel_launch(void* const* d_in, const int* in_sizes, int n_in,
                              void* d_out, int out_size) {
    const float* F  = (const float*)d_in[0];   // (1024, 680)
    const float* D  = (const float*)d_in[1];   // (48, 24, 48, 680)
    const float* qw = (const float*)d_in[2];   // (24,)
    float* out = (float*)d_out;                // (1024, 680) fp32

    dim3 ggrid((DIM + BM - 1) / BM, (DIM + BNJ - 1) / BNJ, SPLITK);  // 6 x 11 x 8
    gram_kernel<<<ggrid, 256>>>(D, qw);

    reduce_kernel<<<(NDIM2 + 255) / 256, 256>>>();
    sym_kernel<<<(NDIM2 + 255) / 256, 256>>>();

    dim3 ogrid(BATCH / BM, (DIM + BM - 1) / BM);                     // 8 x 6
    out_kernel<<<ogrid, 256>>>(F, out);
}

// round 4
// speedup vs baseline: 1.0017x; 1.0017x over previous
#include <cuda_runtime.h>
#include <cuda_bf16.h>
#include <cstdint>
#include <cstddef>

#define BATCH 1024
#define NA 48
#define NB 24
#define DIM 680
#define GTOT (NA*NB*NA)          // 55296
#define SPLITK 8
#define KPS (GTOT/SPLITK)        // 6912
#define BK 32
#define KITERS (KPS/BK)          // 216
#define BM 128                   // i-tile
#define BNJ 64                   // j-tile
#define APITCH 136               // halves: 128 + 8 pad (odd multiple of 8 -> conflict-free ldmatrix)
#define BPITCH 72                // halves: 64 + 8 pad
#define FPITCH 40                // halves: 32 + 8 pad
#define MPITCH 136
#define NDIM2 (DIM*DIM)

// ---- scratch (no allocations allowed) ----
__device__ float gP1[(size_t)SPLITK * NDIM2];   // Zh^T Zh partials
__device__ float gP2[(size_t)SPLITK * NDIM2];   // Zh^T Zl partials
__device__ float gS1[NDIM2];
__device__ float gS2[NDIM2];
__device__ float gM[NDIM2];

// ---------------------------------------------------------------- helpers
__device__ __forceinline__ uint32_t smem_u32(const void* p) {
    return (uint32_t)__cvta_generic_to_shared(p);
}
__device__ __forceinline__ void ldsm4t(uint32_t (&r)[4], uint32_t addr) {
    asm volatile("ldmatrix.sync.aligned.m8n8.x4.trans.shared.b16 {%0,%1,%2,%3}, [%4];"
                 : "=r"(r[0]), "=r"(r[1]), "=r"(r[2]), "=r"(r[3]) : "r"(addr));
}
__device__ __forceinline__ void ldsm4(uint32_t (&r)[4], uint32_t addr) {
    asm volatile("ldmatrix.sync.aligned.m8n8.x4.shared.b16 {%0,%1,%2,%3}, [%4];"
                 : "=r"(r[0]), "=r"(r[1]), "=r"(r[2]), "=r"(r[3]) : "r"(addr));
}
__device__ __forceinline__ void mma_bf16(float (&d)[4], const uint32_t (&a)[4],
                                         uint32_t b0, uint32_t b1) {
    asm volatile(
        "mma.sync.aligned.m16n8k16.row.col.f32.bf16.bf16.f32 "
        "{%0,%1,%2,%3}, {%4,%5,%6,%7}, {%8,%9}, {%0,%1,%2,%3};\n"
        : "+f"(d[0]), "+f"(d[1]), "+f"(d[2]), "+f"(d[3])
        : "r"(a[0]), "r"(a[1]), "r"(a[2]), "r"(a[3]), "r"(b0), "r"(b1));
}
__device__ __forceinline__ uint32_t pack2(float x, float y) {
    __nv_bfloat162 h = __floats2bfloat162_rn(x, y);
    return *reinterpret_cast<uint32_t*>(&h);
}
// split z into bf16 hi + bf16 lo
__device__ __forceinline__ void split_bf16(float z, __nv_bfloat16& h, __nv_bfloat16& l) {
    h = __float2bfloat16(z);
    l = __float2bfloat16(z - __bfloat162float(h));
}

// ---------------------------------------------------------------- kernel 1
// C1 = Zh^T Zh -> gP1[split], C2 = Zh^T Zl -> gP2[split],  Z = sqrt(w) * D
extern "C" __global__ void __launch_bounds__(256)
gram_kernel(const float* __restrict__ D, const float* __restrict__ qw) {
    __shared__ __nv_bfloat16 sA[2][BK * APITCH];
    __shared__ __nv_bfloat16 sBh[2][BK * BPITCH];
    __shared__ __nv_bfloat16 sBl[2][BK * BPITCH];
    __shared__ float sqw[NB];

    const int tid   = threadIdx.x;
    const int ibase = blockIdx.x * BM;
    const int jbase = blockIdx.y * BNJ;
    const int g0    = blockIdx.z * KPS;

    if (tid < NB) sqw[tid] = sqrtf(qw[tid]);
    __syncthreads();

    // global-load mapping
    const int  ca = ibase + (tid & 31) * 4;   // A: 32 float4 per row, 8 rows/pass x4
    const int  cb = jbase + (tid & 15) * 4;   // B: 16 float4 per row, 16 rows/pass x2
    const bool avalid = ca < DIM;
    const bool bvalid = cb < DIM;
    const int  rA = tid >> 5;
    const int  rB = tid >> 4;

    // fragment mapping
    const int lane = tid & 31, warp = tid >> 5;
    const int wm  = (warp & 1) * 64;
    const int wn  = (warp >> 1) * 32;          // 0,32 -> C1 ; 64,96 -> C2
    const int wnl = wn & 63;
    const bool useLo = (wn >= 64);
    const int group = lane >> 2, tig = lane & 3;
    const int arow = (lane & 7) + ((lane & 16) ? 8 : 0);
    const int acol = (lane & 8) ? 8 : 0;
    const int brow = (lane & 7) + ((lane & 8) ? 8 : 0);
    const int bcol = (lane & 16) ? 8 : 0;

    const uint32_t aU[2]  = { smem_u32(sA[0]),  smem_u32(sA[1])  };
    const uint32_t bhU[2] = { smem_u32(sBh[0]), smem_u32(sBh[1]) };
    const uint32_t blU[2] = { smem_u32(sBl[0]), smem_u32(sBl[1]) };

    float acc[4][4][4];
#pragma unroll
    for (int mi = 0; mi < 4; mi++)
#pragma unroll
        for (int nb = 0; nb < 4; nb++)
#pragma unroll
            for (int r = 0; r < 4; r++) acc[mi][nb][r] = 0.f;

    float4 aP[4], bP[2];

    auto ldg = [&](int it) {
        const int gg = g0 + it * BK;
#pragma unroll
        for (int p = 0; p < 4; p++) {
            int g = gg + rA + 8 * p;
            aP[p] = avalid ? *(const float4*)(D + (size_t)g * DIM + ca)
                           : make_float4(0.f, 0.f, 0.f, 0.f);
        }
#pragma unroll
        for (int p = 0; p < 2; p++) {
            int g = gg + rB + 16 * p;
            bP[p] = bvalid ? *(const float4*)(D + (size_t)g * DIM + cb)
                           : make_float4(0.f, 0.f, 0.f, 0.f);
        }
    };
    auto sts = [&](int buf, int it) {
        const int gg = g0 + it * BK;
#pragma unroll
        for (int p = 0; p < 4; p++) {
            int g = gg + rA + 8 * p;
            float w = sqw[(g / NA) % NB];
            float4 v = aP[p];
            uint2 u;
            u.x = pack2(v.x * w, v.y * w);
            u.y = pack2(v.z * w, v.w * w);
            *(uint2*)&sA[buf][(rA + 8 * p) * APITCH + (tid & 31) * 4] = u;
        }
#pragma unroll
        for (int p = 0; p < 2; p++) {
            int g = gg + rB + 16 * p;
            float w = sqw[(g / NA) % NB];
            float4 v = bP[p];
            __nv_bfloat16 h[4], l[4];
            split_bf16(v.x * w, h[0], l[0]);
            split_bf16(v.y * w, h[1], l[1]);
            split_bf16(v.z * w, h[2], l[2]);
            split_bf16(v.w * w, h[3], l[3]);
            int off = (rB + 16 * p) * BPITCH + (tid & 15) * 4;
            uint2 uh, ul;
            uh.x = pack2(__bfloat162float(h[0]), __bfloat162float(h[1]));
            uh.y = pack2(__bfloat162float(h[2]), __bfloat162float(h[3]));
            ul.x = pack2(__bfloat162float(l[0]), __bfloat162float(l[1]));
            ul.y = pack2(__bfloat162float(l[2]), __bfloat162float(l[3]));
            *(uint2*)&sBh[buf][off] = uh;
            *(uint2*)&sBl[buf][off] = ul;
        }
    };

    ldg(0);
    sts(0, 0);
    __syncthreads();

    for (int it = 0; it < KITERS; ++it) {
        const int cur = it & 1;
        if (it + 1 < KITERS) ldg(it + 1);

        const uint32_t abase = aU[cur];
        const uint32_t bbase = useLo ? blU[cur] : bhU[cur];
#pragma unroll
        for (int kk = 0; kk < BK; kk += 16) {
            uint32_t A4[4][4], B4[2][4];
#pragma unroll
            for (int mi = 0; mi < 4; mi++)
                ldsm4t(A4[mi], abase + 2u * ((kk + arow) * APITCH + wm + 16 * mi + acol));
#pragma unroll
            for (int h = 0; h < 2; h++)
                ldsm4t(B4[h], bbase + 2u * ((kk + brow) * BPITCH + wnl + 16 * h + bcol));
#pragma unroll
            for (int mi = 0; mi < 4; mi++)
#pragma unroll
                for (int nb = 0; nb < 4; nb++) {
                    const int h = nb >> 1, pr = (nb & 1) * 2;
                    mma_bf16(acc[mi][nb], A4[mi], B4[h][pr], B4[h][pr + 1]);
                }
        }
        if (it + 1 < KITERS) sts((it + 1) & 1, it + 1);
        __syncthreads();
    }

    // epilogue: write C1 / C2 partials
    float* P = (useLo ? gP2 : gP1) + (size_t)blockIdx.z * NDIM2;
#pragma unroll
    for (int mi = 0; mi < 4; mi++) {
        int i1 = ibase + wm + 16 * mi + group;
        int i2 = i1 + 8;
#pragma unroll
        for (int nb = 0; nb < 4; nb++) {
            int j0 = jbase + wnl + 8 * nb + 2 * tig;
            if (j0 < DIM) {
                if (i1 < DIM) {
                    P[(size_t)i1 * DIM + j0]     = acc[mi][nb][0];
                    P[(size_t)i1 * DIM + j0 + 1] = acc[mi][nb][1];
                }
                if (i2 < DIM) {
                    P[(size_t)i2 * DIM + j0]     = acc[mi][nb][2];
                    P[(size_t)i2 * DIM + j0 + 1] = acc[mi][nb][3];
                }
            }
        }
    }
}

// ---------------------------------------------------------------- kernel 2
extern "C" __global__ void reduce_kernel() {
    int idx = blockIdx.x * blockDim.x + threadIdx.x;
    if (idx < NDIM2) {
        float s1 = 0.f, s2 = 0.f;
#pragma unroll
        for (int p = 0; p < SPLITK; p++) {
            s1 += gP1[(size_t)p * NDIM2 + idx];
            s2 += gP2[(size_t)p * NDIM2 + idx];
        }
        gS1[idx] = s1;
        gS2[idx] = s2;
    }
}

// ---------------------------------------------------------------- kernel 3
// M = S1 + S2 + S2^T
extern "C" __global__ void sym_kernel() {
    int idx = blockIdx.x * blockDim.x + threadIdx.x;
    if (idx < NDIM2) {
        int i = idx / DIM;
        int j = idx - i * DIM;
        gM[idx] = gS1[idx] + gS2[idx] + gS2[(size_t)j * DIM + i];
    }
}

// ---------------------------------------------------------------- kernel 4
// out = F @ M  with 3-term bf16 split: Fh*Mh + Fh*Ml + Fl*Mh
extern "C" __global__ void __launch_bounds__(256)
out_kernel(const float* __restrict__ F, float* __restrict__ out) {
    __shared__ __nv_bfloat16 sFh[BM * FPITCH], sFl[BM * FPITCH];
    __shared__ __nv_bfloat16 sMh[BK * MPITCH], sMl[BK * MPITCH];

    const int tid   = threadIdx.x;
    const int nbase = blockIdx.x * BM;     // 1024/128 exact
    const int ibase = blockIdx.y * BM;     // 6 * 128 = 768 padded

    const int lane = tid & 31, warp = tid >> 5;
    const int wm = (warp & 1) * 64;
    const int wn = (warp >> 1) * 32;
    const int group = lane >> 2, tig = lane & 3;
    // non-trans A frag offsets (F stored [m][k])
    const int frow = ((lane & 8) ? 8 : 0) + (lane & 7);
    const int fcol = (lane & 16) ? 8 : 0;
    // trans B frag offsets (M stored [k][n])
    const int brow = (lane & 7) + ((lane & 8) ? 8 : 0);
    const int bcol = (lane & 16) ? 8 : 0;

    const uint32_t fhU = smem_u32(sFh), flU = smem_u32(sFl);
    const uint32_t mhU = smem_u32(sMh), mlU = smem_u32(sMl);

    float acc[4][4][4];
#pragma unroll
    for (int mi = 0; mi < 4; mi++)
#pragma unroll
        for (int nb = 0; nb < 4; nb++)
#pragma unroll
            for (int r = 0; r < 4; r++) acc[mi][nb][r] = 0.f;

    const int NIT = (DIM + BK - 1) / BK;  // 22

    for (int it = 0; it < NIT; ++it) {
        const int k0 = it * BK;
        // load F tile [128 n][32 k]
        {
            const int c = (tid & 7) * 4;
            const bool v = (k0 + c) < DIM;
#pragma unroll
            for (int p = 0; p < 4; p++) {
                int row = (tid >> 3) + 32 * p;
                float4 f = v ? *(const float4*)(F + (size_t)(nbase + row) * DIM + k0 + c)
                             : make_float4(0.f, 0.f, 0.f, 0.f);
                __nv_bfloat16 h[4], l[4];
                split_bf16(f.x, h[0], l[0]);
                split_bf16(f.y, h[1], l[1]);
                split_bf16(f.z, h[2], l[2]);
                split_bf16(f.w, h[3], l[3]);
                int off = row * FPITCH + c;
                uint2 uh, ul;
                uh.x = pack2(__bfloat162float(h[0]), __bfloat162float(h[1]));
                uh.y = pack2(__bfloat162float(h[2]), __bfloat162float(h[3]));
                ul.x = pack2(__bfloat162float(l[0]), __bfloat162float(l[1]));
                ul.y = pack2(__bfloat162float(l[2]), __bfloat162float(l[3]));
                *(uint2*)&sFh[off] = uh;
                *(uint2*)&sFl[off] = ul;
            }
        }
        // load M tile [32 k][128 i]
        {
            const int c = (tid & 31) * 4;
            const bool cv = (ibase + c) < DIM;
#pragma unroll
            for (int p = 0; p < 4; p++) {
                int r = (tid >> 5) + 8 * p;
                int j = k0 + r;
                bool v = cv && (j < DIM);
                float4 m = v ? *(const float4*)(gM + (size_t)j * DIM + ibase + c)
                             : make_float4(0.f, 0.f, 0.f, 0.f);
                __nv_bfloat16 h[4], l[4];
                split_bf16(m.x, h[0], l[0]);
                split_bf16(m.y, h[1], l[1]);
                split_bf16(m.z, h[2], l[2]);
                split_bf16(m.w, h[3], l[3]);
                int off = r * MPITCH + c;
                uint2 uh, ul;
                uh.x = pack2(__bfloat162float(h[0]), __bfloat162float(h[1]));
                uh.y = pack2(__bfloat162float(h[2]), __bfloat162float(h[3]));
                ul.x = pack2(__bfloat162float(l[0]), __bfloat162float(l[1]));
                ul.y = pack2(__bfloat162float(l[2]), __bfloat162float(l[3]));
                *(uint2*)&sMh[off] = uh;
                *(uint2*)&sMl[off] = ul;
            }
        }
        __syncthreads();

#pragma unroll
        for (int kk = 0; kk < BK; kk += 16) {
            uint32_t Ah[4][4], Al[4][4], Bh[2][4], Bl[2][4];
#pragma unroll
            for (int mi = 0; mi < 4; mi++) {
                uint32_t off = 2u * ((wm + 16 * mi + frow) * FPITCH + kk + fcol);
                ldsm4(Ah[mi], fhU + off);
                ldsm4(Al[mi], flU + off);
            }
#pragma unroll
            for (int h = 0; h < 2; h++) {
                uint32_t off = 2u * ((kk + brow) * MPITCH + wn + 16 * h + bcol);
                ldsm4t(Bh[h], mhU + off);
                ldsm4t(Bl[h], mlU + off);
            }
#pragma unroll
            for (int mi = 0; mi < 4; mi++)
#pragma unroll
                for (int nb = 0; nb < 4; nb++) {
                    const int h = nb >> 1, pr = (nb & 1) * 2;
                    mma_bf16(acc[mi][nb], Ah[mi], Bh[h][pr], Bh[h][pr + 1]);
                    mma_bf16(acc[mi][nb], Ah[mi], Bl[h][pr], Bl[h][pr + 1]);
                    mma_bf16(acc[mi][nb], Al[mi], Bh[h][pr], Bh[h][pr + 1]);
                }
        }
        __syncthreads();
    }

#pragma unroll
    for (int mi = 0; mi < 4; mi++) {
        int n1 = nbase + wm + 16 * mi + group;
        int n2 = n1 + 8;
#pragma unroll
        for (int nb = 0; nb < 4; nb++) {
            int i0 = ibase + wn + 8 * nb + 2 * tig;
            if (i0 < DIM) {
                out[(size_t)n1 * DIM + i0]     = acc[mi][nb][0];
                out[(size_t)n1 * DIM + i0 + 1] = acc[mi][nb][1];
                out[(size_t)n2 * DIM + i0]     = acc[mi][nb][2];
                out[(size_t)n2 * DIM + i0 + 1] = acc[mi][nb][3];
            }
        }
    }
}

// ---------------------------------------------------------------- launch
extern "C" void kernel_launch(void* const* d_in, const int* in_sizes, int n_in,
                              void* d_out, int out_size) {
    const float* F  = (const float*)d_in[0];   // (1024, 680)
    const float* D  = (const float*)d_in[1];   // (48, 24, 48, 680)
    const float* qw = (const float*)d_in[2];   // (24,)
    float* out = (float*)d_out;                // (1024, 680) fp32

    dim3 ggrid((DIM + BM - 1) / BM, (DIM + BNJ - 1) / BNJ, SPLITK);  // 6 x 11 x 8
    gram_kernel<<<ggrid, 256>>>(D, qw);

    reduce_kernel<<<(NDIM2 + 255) / 256, 256>>>();
    sym_kernel<<<(NDIM2 + 255) / 256, 256>>>();

    dim3 ogrid(BATCH / BM, (DIM + BM - 1) / BM);                     // 8 x 6
    out_kernel<<<ogrid, 256>>>(F, out);
}

// round 7
// speedup vs baseline: 1.2118x; 1.2097x over previous
#include <cuda_runtime.h>
#include <cuda_bf16.h>
#include <cstdint>
#include <cstddef>

#define BATCH 1024
#define NA 48
#define NB 24
#define DIM 680
#define DIMP 768                 // padded feature count
#define GTOT (NA*NB*NA)          // 55296
#define NDIM2 (DIM*DIM)

// ---- gram config (legacy mma.sync path) ----
#define SPLITK 8
#define KPS (GTOT/SPLITK)        // 6912
#define GBK 32
#define TOTIT (KPS/GBK)          // 216
#define NSTG 6
#define GBM 256                  // i rows per tile (A)
#define GBN 128                  // j rows per tile (B)
#define GPITCH 40                // bf16 pitch: 32 + 8 pad (80B rows, 16B-aligned, conflict-free)
#define ASTG (GBM*GPITCH*2)      // 20480 B
#define BSTG (GBN*GPITCH*2)      // 10240 B
#define STAGEB (ASTG+BSTG)       // 30720 B
#define NTILES 30
#define TILE_ELEMS (GBM*GBN)     // 32768

// ---- out_kernel config (unchanged from passing round) ----
#define BM 128
#define BK 32
#define FPITCH 40
#define MPITCH 136

// ---- scratch (no allocations allowed) ----
__device__ __nv_bfloat16 gZh[(size_t)DIMP * GTOT];   // ~85MB
__device__ __nv_bfloat16 gZl[(size_t)DIMP * GTOT];   // ~85MB
__device__ float gP[(size_t)NTILES * SPLITK * TILE_ELEMS];  // 31.5MB
__device__ float gS1[NDIM2];
__device__ float gS2[NDIM2];
__device__ float gM[NDIM2];

// tile table: C1 (pass0, Zh*Zh) on 12 tiles with nj>=2*mi ; C2 (pass1, Zh*Zl) on all 18
__constant__ int cMI[NTILES] = {0,0,0,0,0,0, 1,1,1,1, 2,2,
                                0,0,0,0,0,0, 1,1,1,1,1,1, 2,2,2,2,2,2};
__constant__ int cNJ[NTILES] = {0,1,2,3,4,5, 2,3,4,5, 4,5,
                                0,1,2,3,4,5, 0,1,2,3,4,5, 0,1,2,3,4,5};
__constant__ int cPASS[NTILES] = {0,0,0,0,0,0,0,0,0,0,0,0,
                                  1,1,1,1,1,1,1,1,1,1,1,1,1,1,1,1,1,1};

// ---------------------------------------------------------------- helpers
__device__ __forceinline__ uint32_t smem_u32(const void* p) {
    return (uint32_t)__cvta_generic_to_shared(p);
}
__device__ __forceinline__ void split_bf16(float z, __nv_bfloat16& h, __nv_bfloat16& l) {
    h = __float2bfloat16(z);
    l = __float2bfloat16(z - __bfloat162float(h));
}
__device__ __forceinline__ uint32_t pack2h(__nv_bfloat16 a, __nv_bfloat16 b) {
    uint16_t ua = *reinterpret_cast<uint16_t*>(&a);
    uint16_t ub = *reinterpret_cast<uint16_t*>(&b);
    return (uint32_t)ua | ((uint32_t)ub << 16);
}
__device__ __forceinline__ void cp_async16(uint32_t dst, const void* src) {
    asm volatile("cp.async.cg.shared.global [%0], [%1], 16;\n" :: "r"(dst), "l"(src));
}
__device__ __forceinline__ void cp_commit() {
    asm volatile("cp.async.commit_group;\n" ::: "memory");
}
__device__ __forceinline__ void ldsm4(uint32_t (&r)[4], uint32_t addr) {
    asm volatile("ldmatrix.sync.aligned.m8n8.x4.shared.b16 {%0,%1,%2,%3}, [%4];"
                 : "=r"(r[0]), "=r"(r[1]), "=r"(r[2]), "=r"(r[3]) : "r"(addr));
}
__device__ __forceinline__ void ldsm4t(uint32_t (&r)[4], uint32_t addr) {
    asm volatile("ldmatrix.sync.aligned.m8n8.x4.trans.shared.b16 {%0,%1,%2,%3}, [%4];"
                 : "=r"(r[0]), "=r"(r[1]), "=r"(r[2]), "=r"(r[3]) : "r"(addr));
}
__device__ __forceinline__ void mma_bf16(float (&d)[4], const uint32_t (&a)[4],
                                         uint32_t b0, uint32_t b1) {
    asm volatile(
        "mma.sync.aligned.m16n8k16.row.col.f32.bf16.bf16.f32 "
        "{%0,%1,%2,%3}, {%4,%5,%6,%7}, {%8,%9}, {%0,%1,%2,%3};\n"
        : "+f"(d[0]), "+f"(d[1]), "+f"(d[2]), "+f"(d[3])
        : "r"(a[0]), "r"(a[1]), "r"(a[2]), "r"(a[3]), "r"(b0), "r"(b1));
}

// ---------------------------------------------------------------- kernel 1
// transpose + weight + bf16 split: gZh/gZl[i][g] = split( sqrt(qw_g) * D[g][i] )
#define TPP 65
extern "C" __global__ void __launch_bounds__(256)
transpose_kernel(const float* __restrict__ D, const float* __restrict__ qw) {
    __shared__ float s[64][TPP];
    __shared__ float sqw[NB];
    const int tid = threadIdx.x;
    if (tid < NB) sqw[tid] = sqrtf(qw[tid]);
    __syncthreads();
    const int gbase = blockIdx.x * 64;
    const int ibase = blockIdx.y * 64;

#pragma unroll
    for (int p = 0; p < 4; p++) {
        int g_l = (tid >> 4) + 16 * p;
        int i_l = (tid & 15) * 4;
        int g = gbase + g_l;
        float w = sqw[(g / NA) % NB];
        float4 v = (ibase + i_l < DIM)
                 ? *(const float4*)(D + (size_t)g * DIM + ibase + i_l)
                 : make_float4(0.f, 0.f, 0.f, 0.f);
        s[g_l][i_l]     = v.x * w;
        s[g_l][i_l + 1] = v.y * w;
        s[g_l][i_l + 2] = v.z * w;
        s[g_l][i_l + 3] = v.w * w;
    }
    __syncthreads();

    const int i_l = tid >> 2;
    const int gc  = (tid & 3) * 16;
    uint32_t hi[8], lo[8];
#pragma unroll
    for (int q = 0; q < 8; q++) {
        float a = s[gc + 2 * q][i_l];
        float b = s[gc + 2 * q + 1][i_l];
        __nv_bfloat16 ha, la, hb, lb;
        split_bf16(a, ha, la);
        split_bf16(b, hb, lb);
        hi[q] = pack2h(ha, hb);
        lo[q] = pack2h(la, lb);
    }
    size_t ro = (size_t)(ibase + i_l) * GTOT + gbase + gc;
    *(uint4*)(gZh + ro)     = make_uint4(hi[0], hi[1], hi[2], hi[3]);
    *(uint4*)(gZh + ro + 8) = make_uint4(hi[4], hi[5], hi[6], hi[7]);
    *(uint4*)(gZl + ro)     = make_uint4(lo[0], lo[1], lo[2], lo[3]);
    *(uint4*)(gZl + ro + 8) = make_uint4(lo[4], lo[5], lo[6], lo[7]);
}

// ---------------------------------------------------------------- kernel 2
// legacy-mma gram: tile e, split z -> gP[e][z] = A(256 rows Zh) @ B(128 rows Zh|Zl)^T
extern "C" __global__ void __launch_bounds__(512, 1)
gram_mm() {
    extern __shared__ char dsm[];
    const uint32_t sbase = smem_u32(dsm);

    const int e     = blockIdx.x;
    const int split = blockIdx.y;
    const int ibase = cMI[e] * GBM;
    const int jbase = cNJ[e] * GBN;
    const size_t g0 = (size_t)split * KPS;
    const __nv_bfloat16* Brows = cPASS[e] ? gZl : gZh;

    const int tid  = threadIdx.x;
    const int lane = tid & 31, warp = tid >> 5;
    const int wmB  = (warp & 3) * 64;     // warp m-base within 256
    const int wnB  = (warp >> 2) * 32;    // warp n-base within 128
    const int group = lane >> 2, tig = lane & 3;
    const int frow = lane & 15;
    const int fcol = (lane & 16) ? 8 : 0;

    float acc[4][4][4];
#pragma unroll
    for (int mi = 0; mi < 4; mi++)
#pragma unroll
        for (int nb = 0; nb < 4; nb++)
#pragma unroll
            for (int r = 0; r < 4; r++) acc[mi][nb][r] = 0.f;

    // fill: 1536 16B chunks (A: 1024, B: 512), 3 per thread
    auto fill = [&](int it) {
        const uint32_t stg = sbase + (uint32_t)(it % NSTG) * STAGEB;
        const size_t gofs = g0 + (size_t)it * GBK;
        {
            int c = tid;                          // A chunk 0..511
            int row = c >> 2, col16 = c & 3;
            cp_async16(stg + row * 80 + col16 * 16,
                       gZh + (size_t)(ibase + row) * GTOT + gofs + col16 * 8);
            c = tid + 512;                        // A chunk 512..1023
            row = c >> 2; col16 = c & 3;
            cp_async16(stg + row * 80 + col16 * 16,
                       gZh + (size_t)(ibase + row) * GTOT + gofs + col16 * 8);
            c = tid;                              // B chunk 0..511
            row = c >> 2; col16 = c & 3;
            cp_async16(stg + ASTG + row * 80 + col16 * 16,
                       Brows + (size_t)(jbase + row) * GTOT + gofs + col16 * 8);
        }
        cp_commit();
    };

#pragma unroll
    for (int s = 0; s < NSTG - 1; s++) fill(s);   // prologue: 5 groups

    for (int it = 0; it < TOTIT; ++it) {
        if (it <= TOTIT - 5)
            asm volatile("cp.async.wait_group 4;\n" ::: "memory");
        else if (it == TOTIT - 4)
            asm volatile("cp.async.wait_group 3;\n" ::: "memory");
        else if (it == TOTIT - 3)
            asm volatile("cp.async.wait_group 2;\n" ::: "memory");
        else if (it == TOTIT - 2)
            asm volatile("cp.async.wait_group 1;\n" ::: "memory");
        else
            asm volatile("cp.async.wait_group 0;\n" ::: "memory");
        __syncthreads();

        const uint32_t stg = sbase + (uint32_t)(it % NSTG) * STAGEB;
        const uint32_t aU = stg, bU = stg + ASTG;
#pragma unroll
        for (int kk = 0; kk < GBK; kk += 16) {
            uint32_t A4[4][4], B4[2][4];
#pragma unroll
            for (int mi = 0; mi < 4; mi++)
                ldsm4(A4[mi], aU + 2u * ((wmB + 16 * mi + frow) * GPITCH + kk + fcol));
#pragma unroll
            for (int h = 0; h < 2; h++)
                ldsm4(B4[h], bU + 2u * ((wnB + 16 * h + frow) * GPITCH + kk + fcol));
#pragma unroll
            for (int mi = 0; mi < 4; mi++)
#pragma unroll
                for (int nb = 0; nb < 4; nb++)
                    mma_bf16(acc[mi][nb], A4[mi],
                             B4[nb >> 1][nb & 1], B4[nb >> 1][(nb & 1) + 2]);
        }
        const int f = it + (NSTG - 1);
        if (f < TOTIT) fill(f);
    }

    // epilogue: per-tile partial [256][128] fp32
    float* P = gP + ((size_t)(e * SPLITK + split)) * TILE_ELEMS;
#pragma unroll
    for (int mi = 0; mi < 4; mi++) {
        int r1 = wmB + 16 * mi + group;
        int r2 = r1 + 8;
#pragma unroll
        for (int nb = 0; nb < 4; nb++) {
            int c0 = wnB + 8 * nb + 2 * tig;
            P[(size_t)r1 * GBN + c0]     = acc[mi][nb][0];
            P[(size_t)r1 * GBN + c0 + 1] = acc[mi][nb][1];
            P[(size_t)r2 * GBN + c0]     = acc[mi][nb][2];
            P[(size_t)r2 * GBN + c0 + 1] = acc[mi][nb][3];
        }
    }
}

// ---------------------------------------------------------------- kernel 3
extern "C" __global__ void reduce_tc() {
    size_t idx = (size_t)blockIdx.x * 256 + threadIdx.x;
    if (idx >= (size_t)NTILES * TILE_ELEMS) return;
    const int e  = (int)(idx >> 15);
    const int rc = (int)(idx & 32767);
    float sum = 0.f;
#pragma unroll
    for (int p = 0; p < SPLITK; p++)
        sum += gP[(((size_t)(e * SPLITK + p)) << 15) + rc];
    const int r = rc >> 7, c = rc & 127;     // [256][128]
    const int i = cMI[e] * GBM + r;
    const int j = cNJ[e] * GBN + c;
    if (i < DIM && j < DIM)
        (cPASS[e] ? gS2 : gS1)[(size_t)i * DIM + j] = sum;
}

// ---------------------------------------------------------------- kernel 4
// M = C1(sym) + C2 + C2^T ; C1 tile (bi,bj) computed iff bj >= 2*bi
extern "C" __global__ void sym_kernel() {
    int idx = blockIdx.x * blockDim.x + threadIdx.x;
    if (idx < NDIM2) {
        int i = idx / DIM;
        int j = idx - i * DIM;
        float c1 = ((j >> 7) >= 2 * (i >> 8)) ? gS1[idx] : gS1[(size_t)j * DIM + i];
        gM[idx] = c1 + gS2[idx] + gS2[(size_t)j * DIM + i];
    }
}

// ---------------------------------------------------------------- kernel 5
// out = F @ M  (3-term bf16 split, legacy mma path — unchanged from passing round)
extern "C" __global__ void __launch_bounds__(256)
out_kernel(const float* __restrict__ F, float* __restrict__ out) {
    __shared__ __nv_bfloat16 sFh[BM * FPITCH], sFl[BM * FPITCH];
    __shared__ __nv_bfloat16 sMh[BK * MPITCH], sMl[BK * MPITCH];

    const int tid   = threadIdx.x;
    const int nbase = blockIdx.x * BM;
    const int ibase = blockIdx.y * BM;

    const int lane = tid & 31, warp = tid >> 5;
    const int wm = (warp & 1) * 64;
    const int wn = (warp >> 1) * 32;
    const int group = lane >> 2, tig = lane & 3;
    const int frow = ((lane & 8) ? 8 : 0) + (lane & 7);
    const int fcol = (lane & 16) ? 8 : 0;
    const int brow = (lane & 7) + ((lane & 8) ? 8 : 0);
    const int bcol = (lane & 16) ? 8 : 0;

    const uint32_t fhU = smem_u32(sFh), flU = smem_u32(sFl);
    const uint32_t mhU = smem_u32(sMh), mlU = smem_u32(sMl);

    float acc[4][4][4];
#pragma unroll
    for (int mi = 0; mi < 4; mi++)
#pragma unroll
        for (int nb = 0; nb < 4; nb++)
#pragma unroll
            for (int r = 0; r < 4; r++) acc[mi][nb][r] = 0.f;

    const int NIT = (DIM + BK - 1) / BK;

    for (int it = 0; it < NIT; ++it) {
        const int k0 = it * BK;
        {
            const int c = (tid & 7) * 4;
            const bool v = (k0 + c) < DIM;
#pragma unroll
            for (int p = 0; p < 4; p++) {
                int row = (tid >> 3) + 32 * p;
                float4 f = v ? *(const float4*)(F + (size_t)(nbase + row) * DIM + k0 + c)
                             : make_float4(0.f, 0.f, 0.f, 0.f);
                __nv_bfloat16 h[4], l[4];
                split_bf16(f.x, h[0], l[0]);
                split_bf16(f.y, h[1], l[1]);
                split_bf16(f.z, h[2], l[2]);
                split_bf16(f.w, h[3], l[3]);
                int off = row * FPITCH + c;
                *(uint2*)&sFh[off] = make_uint2(pack2h(h[0], h[1]), pack2h(h[2], h[3]));
                *(uint2*)&sFl[off] = make_uint2(pack2h(l[0], l[1]), pack2h(l[2], l[3]));
            }
        }
        {
            const int c = (tid & 31) * 4;
            const bool cv = (ibase + c) < DIM;
#pragma unroll
            for (int p = 0; p < 4; p++) {
                int r = (tid >> 5) + 8 * p;
                int j = k0 + r;
                bool v = cv && (j < DIM);
                float4 m = v ? *(const float4*)(gM + (size_t)j * DIM + ibase + c)
                             : make_float4(0.f, 0.f, 0.f, 0.f);
                __nv_bfloat16 h[4], l[4];
                split_bf16(m.x, h[0], l[0]);
                split_bf16(m.y, h[1], l[1]);
                split_bf16(m.z, h[2], l[2]);
                split_bf16(m.w, h[3], l[3]);
                int off = r * MPITCH + c;
                *(uint2*)&sMh[off] = make_uint2(pack2h(h[0], h[1]), pack2h(h[2], h[3]));
                *(uint2*)&sMl[off] = make_uint2(pack2h(l[0], l[1]), pack2h(l[2], l[3]));
            }
        }
        __syncthreads();

#pragma unroll
        for (int kk = 0; kk < BK; kk += 16) {
            uint32_t Ah[4][4], Al[4][4], Bh[2][4], Bl[2][4];
#pragma unroll
            for (int mi = 0; mi < 4; mi++) {
                uint32_t off = 2u * ((wm + 16 * mi + frow) * FPITCH + kk + fcol);
                ldsm4(Ah[mi], fhU + off);
                ldsm4(Al[mi], flU + off);
            }
#pragma unroll
            for (int h = 0; h < 2; h++) {
                uint32_t off = 2u * ((kk + brow) * MPITCH + wn + 16 * h + bcol);
                ldsm4t(Bh[h], mhU + off);
                ldsm4t(Bl[h], mlU + off);
            }
#pragma unroll
            for (int mi = 0; mi < 4; mi++)
#pragma unroll
                for (int nb = 0; nb < 4; nb++) {
                    const int h = nb >> 1, pr = (nb & 1) * 2;
                    mma_bf16(acc[mi][nb], Ah[mi], Bh[h][pr], Bh[h][pr + 1]);
                    mma_bf16(acc[mi][nb], Ah[mi], Bl[h][pr], Bl[h][pr + 1]);
                    mma_bf16(acc[mi][nb], Al[mi], Bh[h][pr], Bh[h][pr + 1]);
                }
        }
        __syncthreads();
    }

#pragma unroll
    for (int mi = 0; mi < 4; mi++) {
        int n1 = nbase + wm + 16 * mi + group;
        int n2 = n1 + 8;
#pragma unroll
        for (int nb = 0; nb < 4; nb++) {
            int i0 = ibase + wn + 8 * nb + 2 * tig;
            if (i0 < DIM) {
                out[(size_t)n1 * DIM + i0]     = acc[mi][nb][0];
                out[(size_t)n1 * DIM + i0 + 1] = acc[mi][nb][1];
                out[(size_t)n2 * DIM + i0]     = acc[mi][nb][2];
                out[(size_t)n2 * DIM + i0 + 1] = acc[mi][nb][3];
            }
        }
    }
}

// ---------------------------------------------------------------- launch
extern "C" void kernel_launch(void* const* d_in, const int* in_sizes, int n_in,
                              void* d_out, int out_size) {
    const float* F  = (const float*)d_in[0];   // (1024, 680)
    const float* D  = (const float*)d_in[1];   // (48, 24, 48, 680)
    const float* qw = (const float*)d_in[2];   // (24,)
    float* out = (float*)d_out;                // (1024, 680) fp32

    const int gram_smem = NSTG * STAGEB;       // 184320 B
    cudaFuncSetAttribute(gram_mm, cudaFuncAttributeMaxDynamicSharedMemorySize, gram_smem);

    transpose_kernel<<<dim3(GTOT / 64, DIMP / 64), 256>>>(D, qw);

    gram_mm<<<dim3(NTILES, SPLITK), 512, gram_smem>>>();

    reduce_tc<<<(NTILES * TILE_ELEMS + 255) / 256, 256>>>();
    sym_kernel<<<(NDIM2 + 255) / 256, 256>>>();

    dim3 ogrid(BATCH / BM, (DIM + BM - 1) / BM);        // 8 x 6
    out_kernel<<<ogrid, 256>>>(F, out);
}

// round 8
// speedup vs baseline: 1.4715x; 1.2144x over previous
#include <cuda_runtime.h>
#include <cuda_bf16.h>
#include <cstdint>
#include <cstddef>

#define BATCH 1024
#define NA 48
#define NB 24
#define DIM 680
#define DIMP 768                 // padded feature count
#define GTOT (NA*NB*NA)          // 55296
#define NDIM2 (DIM*DIM)

// ---- gram config ----
#define SPLITK 8
#define KPS (GTOT/SPLITK)        // 6912
#define GBK 32
#define TOTIT (KPS/GBK)          // 216
#define NSTG 4
#define GBM 128
#define GBN 128
#define GPITCH 40                // bf16 pitch: 32 + 8 pad (80B rows, conflict-free)
#define ASTG (GBM*GPITCH*2)      // 10240 B
#define STAGEB (2*ASTG)          // 20480 B
#define NTILES 57                // 21 C1 (j>=i) + 36 C2
#define TILE_ELEMS (GBM*GBN)     // 16384

// ---- out_kernel config ----
#define OBM 64                   // F rows per CTA
#define OBN 128                  // i cols per CTA
#define BK 32
#define FPITCH 40
#define MPITCH 136

// ---- scratch (no allocations allowed) ----
__device__ __nv_bfloat16 gZh[(size_t)DIMP * GTOT];   // ~85MB
__device__ __nv_bfloat16 gZl[(size_t)DIMP * GTOT];   // ~85MB
__device__ float gP[(size_t)NTILES * SPLITK * TILE_ELEMS];  // ~29.9MB
__device__ float gS1[NDIM2];
__device__ float gS2[NDIM2];
__device__ float gM[NDIM2];

// tile tables: C1 (pass0, Zh*Zh) on j>=i triangle; C2 (pass1, Zh*Zl) on all 36
__constant__ int cMI[NTILES] = {
    0,0,0,0,0,0, 1,1,1,1,1, 2,2,2,2, 3,3,3, 4,4, 5,
    0,0,0,0,0,0, 1,1,1,1,1,1, 2,2,2,2,2,2, 3,3,3,3,3,3, 4,4,4,4,4,4, 5,5,5,5,5,5};
__constant__ int cNJ[NTILES] = {
    0,1,2,3,4,5, 1,2,3,4,5, 2,3,4,5, 3,4,5, 4,5, 5,
    0,1,2,3,4,5, 0,1,2,3,4,5, 0,1,2,3,4,5, 0,1,2,3,4,5, 0,1,2,3,4,5, 0,1,2,3,4,5};
__constant__ int cPASS[NTILES] = {
    0,0,0,0,0,0,0,0,0,0,0,0,0,0,0,0,0,0,0,0,0,
    1,1,1,1,1,1,1,1,1,1,1,1,1,1,1,1,1,1,
    1,1,1,1,1,1,1,1,1,1,1,1,1,1,1,1,1,1};

// ---------------------------------------------------------------- helpers
__device__ __forceinline__ uint32_t smem_u32(const void* p) {
    return (uint32_t)__cvta_generic_to_shared(p);
}
__device__ __forceinline__ void split_bf16(float z, __nv_bfloat16& h, __nv_bfloat16& l) {
    h = __float2bfloat16(z);
    l = __float2bfloat16(z - __bfloat162float(h));
}
__device__ __forceinline__ uint32_t pack2h(__nv_bfloat16 a, __nv_bfloat16 b) {
    uint16_t ua = *reinterpret_cast<uint16_t*>(&a);
    uint16_t ub = *reinterpret_cast<uint16_t*>(&b);
    return (uint32_t)ua | ((uint32_t)ub << 16);
}
__device__ __forceinline__ void cp_async16(uint32_t dst, const void* src) {
    asm volatile("cp.async.cg.shared.global [%0], [%1], 16;\n" :: "r"(dst), "l"(src));
}
__device__ __forceinline__ void cp_commit() {
    asm volatile("cp.async.commit_group;\n" ::: "memory");
}
__device__ __forceinline__ void ldsm4(uint32_t (&r)[4], uint32_t addr) {
    asm volatile("ldmatrix.sync.aligned.m8n8.x4.shared.b16 {%0,%1,%2,%3}, [%4];"
                 : "=r"(r[0]), "=r"(r[1]), "=r"(r[2]), "=r"(r[3]) : "r"(addr));
}
__device__ __forceinline__ void ldsm4t(uint32_t (&r)[4], uint32_t addr) {
    asm volatile("ldmatrix.sync.aligned.m8n8.x4.trans.shared.b16 {%0,%1,%2,%3}, [%4];"
                 : "=r"(r[0]), "=r"(r[1]), "=r"(r[2]), "=r"(r[3]) : "r"(addr));
}
__device__ __forceinline__ void mma_bf16(float (&d)[4], const uint32_t (&a)[4],
                                         uint32_t b0, uint32_t b1) {
    asm volatile(
        "mma.sync.aligned.m16n8k16.row.col.f32.bf16.bf16.f32 "
        "{%0,%1,%2,%3}, {%4,%5,%6,%7}, {%8,%9}, {%0,%1,%2,%3};\n"
        : "+f"(d[0]), "+f"(d[1]), "+f"(d[2]), "+f"(d[3])
        : "r"(a[0]), "r"(a[1]), "r"(a[2]), "r"(a[3]), "r"(b0), "r"(b1));
}

// ---------------------------------------------------------------- kernel 1
// transpose + weight + bf16 split: gZh/gZl[i][g] = split( sqrt(qw_g) * D[g][i] )
#define TPP 65
extern "C" __global__ void __launch_bounds__(256)
transpose_kernel(const float* __restrict__ D, const float* __restrict__ qw) {
    __shared__ float s[64][TPP];
    __shared__ float sqw[NB];
    const int tid = threadIdx.x;
    if (tid < NB) sqw[tid] = sqrtf(qw[tid]);
    __syncthreads();
    const int gbase = blockIdx.x * 64;
    const int ibase = blockIdx.y * 64;

#pragma unroll
    for (int p = 0; p < 4; p++) {
        int g_l = (tid >> 4) + 16 * p;
        int i_l = (tid & 15) * 4;
        int g = gbase + g_l;
        float w = sqw[(g / NA) % NB];
        float4 v = (ibase + i_l < DIM)
                 ? *(const float4*)(D + (size_t)g * DIM + ibase + i_l)
                 : make_float4(0.f, 0.f, 0.f, 0.f);
        s[g_l][i_l]     = v.x * w;
        s[g_l][i_l + 1] = v.y * w;
        s[g_l][i_l + 2] = v.z * w;
        s[g_l][i_l + 3] = v.w * w;
    }
    __syncthreads();

    const int i_l = tid >> 2;
    const int gc  = (tid & 3) * 16;
    uint32_t hi[8], lo[8];
#pragma unroll
    for (int q = 0; q < 8; q++) {
        float a = s[gc + 2 * q][i_l];
        float b = s[gc + 2 * q + 1][i_l];
        __nv_bfloat16 ha, la, hb, lb;
        split_bf16(a, ha, la);
        split_bf16(b, hb, lb);
        hi[q] = pack2h(ha, hb);
        lo[q] = pack2h(la, lb);
    }
    size_t ro = (size_t)(ibase + i_l) * GTOT + gbase + gc;
    *(uint4*)(gZh + ro)     = make_uint4(hi[0], hi[1], hi[2], hi[3]);
    *(uint4*)(gZh + ro + 8) = make_uint4(hi[4], hi[5], hi[6], hi[7]);
    *(uint4*)(gZl + ro)     = make_uint4(lo[0], lo[1], lo[2], lo[3]);
    *(uint4*)(gZl + ro + 8) = make_uint4(lo[4], lo[5], lo[6], lo[7]);
}

// ---------------------------------------------------------------- kernel 2
// gram: tile e, split z -> gP[e][z] = A(128 rows Zh) @ B(128 rows Zh|Zl)^T
// 256 threads, 2 CTAs/SM for cross-CTA latency hiding.
extern "C" __global__ void __launch_bounds__(256, 2)
gram_mm() {
    extern __shared__ char dsm[];
    const uint32_t sbase = smem_u32(dsm);

    const int e     = blockIdx.x;
    const int split = blockIdx.y;
    const int ibase = cMI[e] * GBM;
    const int jbase = cNJ[e] * GBN;
    const size_t g0 = (size_t)split * KPS;
    const __nv_bfloat16* Brows = cPASS[e] ? gZl : gZh;

    const int tid  = threadIdx.x;
    const int lane = tid & 31, warp = tid >> 5;
    const int wmB  = (warp & 1) * 64;
    const int wnB  = (warp >> 1) * 32;
    const int group = lane >> 2, tig = lane & 3;
    const int frow = lane & 15;
    const int fcol = (lane & 16) ? 8 : 0;

    float acc[4][4][4];
#pragma unroll
    for (int mi = 0; mi < 4; mi++)
#pragma unroll
        for (int nb = 0; nb < 4; nb++)
#pragma unroll
            for (int r = 0; r < 4; r++) acc[mi][nb][r] = 0.f;

    // fill: A 512 + B 512 16B chunks, 4 per thread
    auto fill = [&](int it) {
        const uint32_t stg = sbase + (uint32_t)(it & (NSTG - 1)) * STAGEB;
        const size_t gofs = g0 + (size_t)it * GBK;
#pragma unroll
        for (int p = 0; p < 2; p++) {
            int c = tid + 256 * p;
            int row = c >> 2, col16 = c & 3;
            cp_async16(stg + row * 80 + col16 * 16,
                       gZh + (size_t)(ibase + row) * GTOT + gofs + col16 * 8);
            cp_async16(stg + ASTG + row * 80 + col16 * 16,
                       Brows + (size_t)(jbase + row) * GTOT + gofs + col16 * 8);
        }
        cp_commit();
    };

#pragma unroll
    for (int s = 0; s < NSTG - 1; s++) fill(s);   // prologue: 3 groups

    for (int it = 0; it < TOTIT; ++it) {
        if (it <= TOTIT - 3)
            asm volatile("cp.async.wait_group 2;\n" ::: "memory");
        else if (it == TOTIT - 2)
            asm volatile("cp.async.wait_group 1;\n" ::: "memory");
        else
            asm volatile("cp.async.wait_group 0;\n" ::: "memory");
        __syncthreads();

        const uint32_t stg = sbase + (uint32_t)(it & (NSTG - 1)) * STAGEB;
        const uint32_t aU = stg, bU = stg + ASTG;
#pragma unroll
        for (int kk = 0; kk < GBK; kk += 16) {
            uint32_t A4[4][4], B4[2][4];
#pragma unroll
            for (int mi = 0; mi < 4; mi++)
                ldsm4(A4[mi], aU + 2u * ((wmB + 16 * mi + frow) * GPITCH + kk + fcol));
#pragma unroll
            for (int h = 0; h < 2; h++)
                ldsm4(B4[h], bU + 2u * ((wnB + 16 * h + frow) * GPITCH + kk + fcol));
#pragma unroll
            for (int mi = 0; mi < 4; mi++)
#pragma unroll
                for (int nb = 0; nb < 4; nb++)
                    mma_bf16(acc[mi][nb], A4[mi],
                             B4[nb >> 1][nb & 1], B4[nb >> 1][(nb & 1) + 2]);
        }
        const int f = it + (NSTG - 1);
        if (f < TOTIT) fill(f);
    }

    // epilogue: per-tile partial [128][128] fp32
    float* P = gP + ((size_t)(e * SPLITK + split)) * TILE_ELEMS;
#pragma unroll
    for (int mi = 0; mi < 4; mi++) {
        int r1 = wmB + 16 * mi + group;
        int r2 = r1 + 8;
#pragma unroll
        for (int nb = 0; nb < 4; nb++) {
            int c0 = wnB + 8 * nb + 2 * tig;
            P[(size_t)r1 * GBN + c0]     = acc[mi][nb][0];
            P[(size_t)r1 * GBN + c0 + 1] = acc[mi][nb][1];
            P[(size_t)r2 * GBN + c0]     = acc[mi][nb][2];
            P[(size_t)r2 * GBN + c0 + 1] = acc[mi][nb][3];
        }
    }
}

// ---------------------------------------------------------------- kernel 3
extern "C" __global__ void reduce_tc() {
    size_t idx = (size_t)blockIdx.x * 256 + threadIdx.x;
    if (idx >= (size_t)NTILES * TILE_ELEMS) return;
    const int e  = (int)(idx >> 14);
    const int rc = (int)(idx & 16383);
    float sum = 0.f;
#pragma unroll
    for (int p = 0; p < SPLITK; p++)
        sum += gP[(((size_t)(e * SPLITK + p)) << 14) + rc];
    const int r = rc >> 7, c = rc & 127;
    const int i = cMI[e] * GBM + r;
    const int j = cNJ[e] * GBN + c;
    if (i < DIM && j < DIM)
        (cPASS[e] ? gS2 : gS1)[(size_t)i * DIM + j] = sum;
}

// ---------------------------------------------------------------- kernel 4
// M = C1(sym) + C2 + C2^T ; C1 block (bi,bj) computed iff bj >= bi
extern "C" __global__ void sym_kernel() {
    int idx = blockIdx.x * blockDim.x + threadIdx.x;
    if (idx < NDIM2) {
        int i = idx / DIM;
        int j = idx - i * DIM;
        float c1 = ((j >> 7) >= (i >> 7)) ? gS1[idx] : gS1[(size_t)j * DIM + i];
        gM[idx] = c1 + gS2[idx] + gS2[(size_t)j * DIM + i];
    }
}

// ---------------------------------------------------------------- kernel 5
// out = F @ M  (3-term bf16 split; OBM=64 -> 96 CTAs for latency hiding)
extern "C" __global__ void __launch_bounds__(256)
out_kernel(const float* __restrict__ F, float* __restrict__ out) {
    __shared__ __nv_bfloat16 sFh[OBM * FPITCH], sFl[OBM * FPITCH];
    __shared__ __nv_bfloat16 sMh[BK * MPITCH], sMl[BK * MPITCH];

    const int tid   = threadIdx.x;
    const int nbase = blockIdx.x * OBM;
    const int ibase = blockIdx.y * OBN;

    const int lane = tid & 31, warp = tid >> 5;
    const int wm = (warp & 1) * 32;
    const int wn = (warp >> 1) * 32;
    const int group = lane >> 2, tig = lane & 3;
    const int frow = lane & 15;
    const int fcol = (lane & 16) ? 8 : 0;
    const int brow = (lane & 7) + ((lane & 8) ? 8 : 0);
    const int bcol = (lane & 16) ? 8 : 0;

    const uint32_t fhU = smem_u32(sFh), flU = smem_u32(sFl);
    const uint32_t mhU = smem_u32(sMh), mlU = smem_u32(sMl);

    float acc[2][4][4];
#pragma unroll
    for (int mi = 0; mi < 2; mi++)
#pragma unroll
        for (int nb = 0; nb < 4; nb++)
#pragma unroll
            for (int r = 0; r < 4; r++) acc[mi][nb][r] = 0.f;

    const int NIT = (DIM + BK - 1) / BK;

    for (int it = 0; it < NIT; ++it) {
        const int k0 = it * BK;
        {   // F tile: 64 rows x 32 k = 512 float4 chunks, 2 per thread
            const int c = (tid & 7) * 4;
            const bool v = (k0 + c) < DIM;
#pragma unroll
            for (int p = 0; p < 2; p++) {
                int row = (tid >> 3) + 32 * p;
                float4 f = v ? *(const float4*)(F + (size_t)(nbase + row) * DIM + k0 + c)
                             : make_float4(0.f, 0.f, 0.f, 0.f);
                __nv_bfloat16 h[4], l[4];
                split_bf16(f.x, h[0], l[0]);
                split_bf16(f.y, h[1], l[1]);
                split_bf16(f.z, h[2], l[2]);
                split_bf16(f.w, h[3], l[3]);
                int off = row * FPITCH + c;
                *(uint2*)&sFh[off] = make_uint2(pack2h(h[0], h[1]), pack2h(h[2], h[3]));
                *(uint2*)&sFl[off] = make_uint2(pack2h(l[0], l[1]), pack2h(l[2], l[3]));
            }
        }
        {   // M tile: 32 k x 128 i
            const int c = (tid & 31) * 4;
            const bool cv = (ibase + c) < DIM;
#pragma unroll
            for (int p = 0; p < 4; p++) {
                int r = (tid >> 5) + 8 * p;
                int j = k0 + r;
                bool v = cv && (j < DIM);
                float4 m = v ? *(const float4*)(gM + (size_t)j * DIM + ibase + c)
                             : make_float4(0.f, 0.f, 0.f, 0.f);
                __nv_bfloat16 h[4], l[4];
                split_bf16(m.x, h[0], l[0]);
                split_bf16(m.y, h[1], l[1]);
                split_bf16(m.z, h[2], l[2]);
                split_bf16(m.w, h[3], l[3]);
                int off = r * MPITCH + c;
                *(uint2*)&sMh[off] = make_uint2(pack2h(h[0], h[1]), pack2h(h[2], h[3]));
                *(uint2*)&sMl[off] = make_uint2(pack2h(l[0], l[1]), pack2h(l[2], l[3]));
            }
        }
        __syncthreads();

#pragma unroll
        for (int kk = 0; kk < BK; kk += 16) {
            uint32_t Ah[2][4], Al[2][4], Bh[2][4], Bl[2][4];
#pragma unroll
            for (int mi = 0; mi < 2; mi++) {
                uint32_t off = 2u * ((wm + 16 * mi + frow) * FPITCH + kk + fcol);
                ldsm4(Ah[mi], fhU + off);
                ldsm4(Al[mi], flU + off);
            }
#pragma unroll
            for (int h = 0; h < 2; h++) {
                uint32_t off = 2u * ((kk + brow) * MPITCH + wn + 16 * h + bcol);
                ldsm4t(Bh[h], mhU + off);
                ldsm4t(Bl[h], mlU + off);
            }
#pragma unroll
            for (int mi = 0; mi < 2; mi++)
#pragma unroll
                for (int nb = 0; nb < 4; nb++) {
                    const int h = nb >> 1, pr = (nb & 1) * 2;
                    mma_bf16(acc[mi][nb], Ah[mi], Bh[h][pr], Bh[h][pr + 1]);
                    mma_bf16(acc[mi][nb], Ah[mi], Bl[h][pr], Bl[h][pr + 1]);
                    mma_bf16(acc[mi][nb], Al[mi], Bh[h][pr], Bh[h][pr + 1]);
                }
        }
        __syncthreads();
    }

#pragma unroll
    for (int mi = 0; mi < 2; mi++) {
        int n1 = nbase + wm + 16 * mi + group;
        int n2 = n1 + 8;
#pragma unroll
        for (int nb = 0; nb < 4; nb++) {
            int i0 = ibase + wn + 8 * nb + 2 * tig;
            if (i0 < DIM) {
                out[(size_t)n1 * DIM + i0]     = acc[mi][nb][0];
                out[(size_t)n1 * DIM + i0 + 1] = acc[mi][nb][1];
                out[(size_t)n2 * DIM + i0]     = acc[mi][nb][2];
                out[(size_t)n2 * DIM + i0 + 1] = acc[mi][nb][3];
            }
        }
    }
}

// ---------------------------------------------------------------- launch
extern "C" void kernel_launch(void* const* d_in, const int* in_sizes, int n_in,
                              void* d_out, int out_size) {
    const float* F  = (const float*)d_in[0];   // (1024, 680)
    const float* D  = (const float*)d_in[1];   // (48, 24, 48, 680)
    const float* qw = (const float*)d_in[2];   // (24,)
    float* out = (float*)d_out;                // (1024, 680) fp32

    const int gram_smem = NSTG * STAGEB;       // 81920 B
    cudaFuncSetAttribute(gram_mm, cudaFuncAttributeMaxDynamicSharedMemorySize, gram_smem);

    transpose_kernel<<<dim3(GTOT / 64, DIMP / 64), 256>>>(D, qw);

    gram_mm<<<dim3(NTILES, SPLITK), 256, gram_smem>>>();

    reduce_tc<<<(NTILES * TILE_ELEMS + 255) / 256, 256>>>();
    sym_kernel<<<(NDIM2 + 255) / 256, 256>>>();

    dim3 ogrid(BATCH / OBM, (DIM + OBN - 1) / OBN);     // 16 x 6
    out_kernel<<<ogrid, 256>>>(F, out);
}